// round 3
// baseline (speedup 1.0000x reference)
#include <cuda_runtime.h>
#include <math.h>

#define TT   1000
#define BB   512
#define HH   128
#define G4   512
#define KIN  208

// ---------------- device scratch (statics: no allocations allowed) ----------
__device__ float g_pre[(size_t)TT * BB * G4];   // [t][b][512]  ~1.05 GB, reused for pre0 then pre1
__device__ float g_hs0[(size_t)TT * BB * HH];   // [t][b][128]  ~262 MB
__device__ float g_Mcomb[42 * 512];             // combined input-proj weights [k][j]
__device__ float g_bias0[512];
__device__ float g_bias1[512];
__device__ float g_peproj[TT * 512];            // positional-encoding projection [t][j]
__device__ float g_last[BB * HH];

__device__ __forceinline__ float sigf(float x) {
    return __fdividef(1.0f, 1.0f + __expf(-x));
}
__device__ __forceinline__ float tanhfast(float x) {
    float e = __expf(2.0f * x);               // inf-safe: e->inf => 1, e->0 => -1
    return 1.0f - __fdividef(2.0f, e + 1.0f);
}

// ---------------- weight combine -------------------------------------------
// GCN on fixed 2-node graph + self loops, sym-norm: g = 0.5*(x0+x1)@Wgcn + bgcn,
// gcn_feat=[g,g].  Fold everything linear into M[42][512] and bias0[512].
__global__ __launch_bounds__(512) void k_comb(
                       const float* __restrict__ Wgcn, const float* __restrict__ bgcn,
                       const float* __restrict__ Wte,  const float* __restrict__ bte,
                       const float* __restrict__ Wih0, const float* __restrict__ bih0,
                       const float* __restrict__ bhh0, const float* __restrict__ bih1,
                       const float* __restrict__ bhh1) {
    int j = threadIdx.x;                      // 512 threads, one gate row each
    const float* wr = Wih0 + (size_t)j * KIN;
    for (int k = 0; k < 16; k++) {
        float s = 0.f;
        #pragma unroll 4
        for (int d = 0; d < 64; d++) s += Wgcn[k * 64 + d] * (wr[d] + wr[64 + d]);
        g_Mcomb[k * 512 + j] = 0.5f * s;
    }
    for (int k = 0; k < 26; k++) {
        float s = 0.f;
        #pragma unroll 4
        for (int d = 0; d < 64; d++) s += Wte[k * 64 + d] * wr[144 + d];
        g_Mcomb[(16 + k) * 512 + j] = s;
    }
    float b0 = bih0[j] + bhh0[j];
    #pragma unroll 4
    for (int d = 0; d < 64; d++) b0 += bgcn[d] * (wr[d] + wr[64 + d]) + bte[d] * wr[144 + d];
    g_bias0[j] = b0;
    g_bias1[j] = bih1[j] + bhh1[j];
}

// ---------------- positional encoding projection ----------------------------
__global__ __launch_bounds__(256) void k_pe(const float* __restrict__ Wih0) {
    int id = blockIdx.x * blockDim.x + threadIdx.x;
    if (id >= TT * 512) return;
    int t = id >> 9, j = id & 511;
    const float* wr = Wih0 + (size_t)j * KIN + 128;
    float acc = 0.f;
    #pragma unroll
    for (int i = 0; i < 8; i++) {
        float div = expf(-(float)(2 * i) * (9.210340371976184f / 16.0f)); // ln(1e4)/16
        float ang = (float)t * div;
        acc += sinf(ang) * wr[2 * i] + cosf(ang) * wr[2 * i + 1];
    }
    g_peproj[id] = acc;
}

// ---------------- pre0: [t][b][512] = x42 @ M + peproj + bias0 --------------
// one block per t; 64 batch tiles of 8; weights (42x512) staged in SMEM [k][j]
__global__ __launch_bounds__(512) void k_pre0(const float* __restrict__ xs,
                                              const float* __restrict__ xt) {
    extern __shared__ float sm[];
    float* Msm = sm;               // [42][512]
    float* xT  = sm + 42 * 512;    // [42][8] transposed inputs
    int t = blockIdx.x, j = threadIdx.x;
    for (int i = j; i < 42 * 512; i += 512) Msm[i] = g_Mcomb[i];
    float bj = g_bias0[j] + g_peproj[t * 512 + j];
    __syncthreads();
    for (int bt = 0; bt < 64; bt++) {
        int bb = bt * 8;
        if (j < 128) {                       // x_student: (x0+x1), 16 per row
            int b = j >> 4, k = j & 15;
            const float* xp = xs + ((size_t)(bb + b) * TT + t) * 32;
            xT[k * 8 + b] = xp[k] + xp[k + 16];
        } else if (j < 336) {                // x_teacher: 26 per row
            int idx = j - 128; int b = idx / 26, k = idx - b * 26;
            xT[(16 + k) * 8 + b] = xt[((size_t)(bb + b) * TT + t) * 26 + k];
        }
        __syncthreads();
        float a0 = bj, a1 = bj, a2 = bj, a3 = bj, a4 = bj, a5 = bj, a6 = bj, a7 = bj;
        #pragma unroll
        for (int k = 0; k < 42; k++) {
            float w = Msm[k * 512 + j];
            float4 hA = *(const float4*)(xT + k * 8);
            float4 hB = *(const float4*)(xT + k * 8 + 4);
            a0 += w * hA.x; a1 += w * hA.y; a2 += w * hA.z; a3 += w * hA.w;
            a4 += w * hB.x; a5 += w * hB.y; a6 += w * hB.z; a7 += w * hB.w;
        }
        size_t o = ((size_t)t * BB + bb) * G4 + j;
        g_pre[o]          = a0; g_pre[o + G4]     = a1;
        g_pre[o + 2 * G4] = a2; g_pre[o + 3 * G4] = a3;
        g_pre[o + 4 * G4] = a4; g_pre[o + 5 * G4] = a5;
        g_pre[o + 6 * G4] = a6; g_pre[o + 7 * G4] = a7;
        __syncthreads();
    }
}

// ---------------- pre1: [t][b][512] = hs0 @ Wih1^T + bias1 ------------------
// one block per t; hybrid weight store: k<32 regs, k>=32 SMEM [k-32][j]
__global__ __launch_bounds__(512) void k_pre1(const float* __restrict__ Wih1) {
    extern __shared__ float sm[];
    float* Wsm = sm;               // [96][512]
    float* hT  = sm + 96 * 512;    // [128][8]
    int t = blockIdx.x, j = threadIdx.x;
    float wreg[32];
    #pragma unroll
    for (int k = 0; k < 32; k++) wreg[k] = Wih1[(size_t)j * HH + k];
    for (int i = j; i < 96 * 512; i += 512) {
        int kk = i >> 9, jj = i & 511;
        Wsm[i] = Wih1[(size_t)jj * HH + 32 + kk];
    }
    float bj = g_bias1[j];
    __syncthreads();
    for (int bt = 0; bt < 64; bt++) {
        int bb = bt * 8;
        for (int i = j; i < 1024; i += 512) {
            int b = i >> 7, k = i & 127;
            hT[k * 8 + b] = g_hs0[((size_t)t * BB + bb + b) * HH + k];
        }
        __syncthreads();
        float a0 = bj, a1 = bj, a2 = bj, a3 = bj, a4 = bj, a5 = bj, a6 = bj, a7 = bj;
        #pragma unroll
        for (int k = 0; k < 32; k++) {
            float w = wreg[k];
            float4 hA = *(const float4*)(hT + k * 8);
            float4 hB = *(const float4*)(hT + k * 8 + 4);
            a0 += w * hA.x; a1 += w * hA.y; a2 += w * hA.z; a3 += w * hA.w;
            a4 += w * hB.x; a5 += w * hB.y; a6 += w * hB.z; a7 += w * hB.w;
        }
        #pragma unroll 8
        for (int k = 32; k < 128; k++) {
            float w = Wsm[(k - 32) * 512 + j];
            float4 hA = *(const float4*)(hT + k * 8);
            float4 hB = *(const float4*)(hT + k * 8 + 4);
            a0 += w * hA.x; a1 += w * hA.y; a2 += w * hA.z; a3 += w * hA.w;
            a4 += w * hB.x; a5 += w * hB.y; a6 += w * hB.z; a7 += w * hB.w;
        }
        size_t o = ((size_t)t * BB + bb) * G4 + j;
        g_pre[o]          = a0; g_pre[o + G4]     = a1;
        g_pre[o + 2 * G4] = a2; g_pre[o + 3 * G4] = a3;
        g_pre[o + 4 * G4] = a4; g_pre[o + 5 * G4] = a5;
        g_pre[o + 6 * G4] = a6; g_pre[o + 7 * G4] = a7;
        __syncthreads();
    }
}

// ---------------- LSTM recurrence sweep (one layer, all 1000 steps) ---------
// grid = 128 CTAs, each owns 4 batch rows for the whole sequence.
// thread j in [0,512) owns gate row j.  z[b,j] = pre[t,b,j] + dot(h[b,:],Whh[j,:])
// Gate phase: thread j handles unit u=j&127 of batch bq=j>>7, c kept in a register.
__global__ __launch_bounds__(512) void k_lstm(const float* __restrict__ Whh,
                                              int write_hs, int write_last) {
    extern __shared__ float sm[];
    float* Wsm  = sm;                    // [96][512] W^T rows 32..127
    float* zbuf = sm + 96 * 512;         // [512][5] padded (bank-conflict-free)
    float* hT   = zbuf + 512 * 5;        // [128][4] h transposed
    int j  = threadIdx.x;
    int bb = blockIdx.x * 4;
    float wreg[32];
    #pragma unroll
    for (int k = 0; k < 32; k++) wreg[k] = Whh[(size_t)j * HH + k];
    for (int i = j; i < 96 * 512; i += 512) {
        int kk = i >> 9, jj = i & 511;
        Wsm[i] = Whh[(size_t)jj * HH + 32 + kk];
    }
    hT[j] = 0.f;                         // 512 entries, 512 threads
    int u = j & 127, bq = j >> 7;
    float c = 0.f, hlast = 0.f;
    __syncthreads();

    for (int t = 0; t < TT; t++) {
        size_t po = ((size_t)t * BB + bb) * G4 + j;
        float p0 = g_pre[po];
        float p1 = g_pre[po + G4];
        float p2 = g_pre[po + 2 * G4];
        float p3 = g_pre[po + 3 * G4];
        float a0 = 0.f, a1 = 0.f, a2 = 0.f, a3 = 0.f;
        #pragma unroll
        for (int k = 0; k < 32; k++) {
            float w = wreg[k];
            float4 hv = *(const float4*)(hT + k * 4);
            a0 += w * hv.x; a1 += w * hv.y; a2 += w * hv.z; a3 += w * hv.w;
        }
        #pragma unroll 8
        for (int k = 32; k < 128; k++) {
            float w = Wsm[(k - 32) * 512 + j];
            float4 hv = *(const float4*)(hT + k * 4);
            a0 += w * hv.x; a1 += w * hv.y; a2 += w * hv.z; a3 += w * hv.w;
        }
        float* zr = zbuf + j * 5;
        zr[0] = a0 + p0; zr[1] = a1 + p1; zr[2] = a2 + p2; zr[3] = a3 + p3;
        __syncthreads();

        float zi = zbuf[u * 5 + bq];
        float zf = zbuf[(u + 128) * 5 + bq];
        float zg = zbuf[(u + 256) * 5 + bq];
        float zo = zbuf[(u + 384) * 5 + bq];
        c = sigf(zf) * c + sigf(zi) * tanhfast(zg);
        float h = sigf(zo) * tanhfast(c);
        hlast = h;
        hT[u * 4 + bq] = h;
        if (write_hs) g_hs0[((size_t)t * BB + bb + bq) * HH + u] = h;
        __syncthreads();
    }
    if (write_last) g_last[(bb + bq) * HH + u] = hlast;
}

// ---------------- MLP head ---------------------------------------------------
__global__ __launch_bounds__(128) void k_head(
                       const float* __restrict__ W1, const float* __restrict__ b1,
                       const float* __restrict__ W2, const float* __restrict__ b2,
                       const float* __restrict__ W3, const float* __restrict__ b3,
                       float* __restrict__ out) {
    __shared__ float xin[128], y1[128], y2[64];
    int b = blockIdx.x, j = threadIdx.x;     // 128 threads
    xin[j] = g_last[b * HH + j];
    __syncthreads();
    float s = b1[j];
    #pragma unroll 4
    for (int k = 0; k < 128; k++) s += xin[k] * W1[j * 128 + k];
    y1[j] = fmaxf(s, 0.f);
    __syncthreads();
    if (j < 64) {
        float s2 = b2[j];
        #pragma unroll 4
        for (int k = 0; k < 128; k++) s2 += y1[k] * W2[j * 128 + k];
        y2[j] = fmaxf(s2, 0.f);
    }
    __syncthreads();
    if (j < 26) {
        float s3 = b3[j];
        #pragma unroll 4
        for (int k = 0; k < 64; k++) s3 += y2[k] * W3[j * 64 + k];
        out[b * 26 + j] = s3;
    }
}

// ---------------- launch -----------------------------------------------------
extern "C" void kernel_launch(void* const* d_in, const int* in_sizes, int n_in,
                              void* d_out, int out_size) {
    const float* xs   = (const float*)d_in[0];
    const float* xt   = (const float*)d_in[1];
    const float* Wgcn = (const float*)d_in[2];
    const float* bgcn = (const float*)d_in[3];
    const float* Wte  = (const float*)d_in[4];
    const float* bte  = (const float*)d_in[5];
    const float* Wih0 = (const float*)d_in[6];
    const float* Whh0 = (const float*)d_in[7];
    const float* bih0 = (const float*)d_in[8];
    const float* bhh0 = (const float*)d_in[9];
    const float* Wih1 = (const float*)d_in[10];
    const float* Whh1 = (const float*)d_in[11];
    const float* bih1 = (const float*)d_in[12];
    const float* bhh1 = (const float*)d_in[13];
    const float* W1   = (const float*)d_in[14];
    const float* b1   = (const float*)d_in[15];
    const float* W2   = (const float*)d_in[16];
    const float* b2   = (const float*)d_in[17];
    const float* W3   = (const float*)d_in[18];
    const float* b3   = (const float*)d_in[19];

    const int SM_PRE0 = (42 * 512 + 42 * 8) * 4;                  //  87,360 B
    const int SM_PRE1 = (96 * 512 + 128 * 8) * 4;                 // 200,704 B
    const int SM_LSTM = (96 * 512 + 512 * 5 + 128 * 4) * 4;       // 208,896 B
    cudaFuncSetAttribute(k_pre0, cudaFuncAttributeMaxDynamicSharedMemorySize, SM_PRE0);
    cudaFuncSetAttribute(k_pre1, cudaFuncAttributeMaxDynamicSharedMemorySize, SM_PRE1);
    cudaFuncSetAttribute(k_lstm, cudaFuncAttributeMaxDynamicSharedMemorySize, SM_LSTM);

    k_comb<<<1, 512>>>(Wgcn, bgcn, Wte, bte, Wih0, bih0, bhh0, bih1, bhh1);
    k_pe<<<(TT * 512 + 255) / 256, 256>>>(Wih0);
    k_pre0<<<TT, 512, SM_PRE0>>>(xs, xt);
    k_lstm<<<BB / 4, 512, SM_LSTM>>>(Whh0, 1, 0);   // layer 0, emit hs0
    k_pre1<<<TT, 512, SM_PRE1>>>(Wih1);             // overwrites g_pre with pre1
    k_lstm<<<BB / 4, 512, SM_LSTM>>>(Whh1, 0, 1);   // layer 1, emit last h
    k_head<<<BB, 128>>>(W1, b1, W2, b2, W3, b3, (float*)d_out);
}

// round 4
// speedup vs baseline: 1.3445x; 1.3445x over previous
#include <cuda_runtime.h>
#include <math.h>

#define TT   1000
#define BB   512
#define HH   128
#define G4   512
#define KIN  208

typedef unsigned long long u64;

// ---------------- device scratch --------------------------------------------
__device__ float g_pre[(size_t)TT * BB * G4];   // [t][b][512]
__device__ float g_hs0[(size_t)TT * BB * HH];   // [t][b][128]
__device__ float g_Mcomb[42 * 512];
__device__ float g_bias0[512];
__device__ float g_bias1[512];
__device__ float g_peproj[TT * 512];
__device__ float g_last[BB * HH];

// ---------------- f32x2 helpers ---------------------------------------------
#define FFMA2(d, a, b, c) \
    asm("fma.rn.f32x2 %0, %1, %2, %3;" : "=l"(d) : "l"(a), "l"(b), "l"(c))
#define PACK2(d, x) \
    asm("mov.b64 %0, {%1, %1};" : "=l"(d) : "r"(__float_as_uint(x)))
#define UNPK2(lo, hi, x) \
    asm("mov.b64 {%0, %1}, %2;" : "=r"(lo), "=r"(hi) : "l"(x))

__device__ __forceinline__ float sigf(float x) {
    return __fdividef(1.0f, 1.0f + __expf(-x));
}
__device__ __forceinline__ float tanhfast(float x) {
    float e = __expf(2.0f * x);
    return 1.0f - __fdividef(2.0f, e + 1.0f);
}

// ---------------- weight combine (unchanged, passing) ------------------------
__global__ __launch_bounds__(512) void k_comb(
                       const float* __restrict__ Wgcn, const float* __restrict__ bgcn,
                       const float* __restrict__ Wte,  const float* __restrict__ bte,
                       const float* __restrict__ Wih0, const float* __restrict__ bih0,
                       const float* __restrict__ bhh0, const float* __restrict__ bih1,
                       const float* __restrict__ bhh1) {
    int j = threadIdx.x;
    const float* wr = Wih0 + (size_t)j * KIN;
    for (int k = 0; k < 16; k++) {
        float s = 0.f;
        #pragma unroll 4
        for (int d = 0; d < 64; d++) s += Wgcn[k * 64 + d] * (wr[d] + wr[64 + d]);
        g_Mcomb[k * 512 + j] = 0.5f * s;
    }
    for (int k = 0; k < 26; k++) {
        float s = 0.f;
        #pragma unroll 4
        for (int d = 0; d < 64; d++) s += Wte[k * 64 + d] * wr[144 + d];
        g_Mcomb[(16 + k) * 512 + j] = s;
    }
    float b0 = bih0[j] + bhh0[j];
    #pragma unroll 4
    for (int d = 0; d < 64; d++) b0 += bgcn[d] * (wr[d] + wr[64 + d]) + bte[d] * wr[144 + d];
    g_bias0[j] = b0;
    g_bias1[j] = bih1[j] + bhh1[j];
}

// ---------------- positional encoding projection (unchanged) -----------------
__global__ __launch_bounds__(256) void k_pe(const float* __restrict__ Wih0) {
    int id = blockIdx.x * blockDim.x + threadIdx.x;
    if (id >= TT * 512) return;
    int t = id >> 9, j = id & 511;
    const float* wr = Wih0 + (size_t)j * KIN + 128;
    float acc = 0.f;
    #pragma unroll
    for (int i = 0; i < 8; i++) {
        float div = expf(-(float)(2 * i) * (9.210340371976184f / 16.0f));
        float ang = (float)t * div;
        acc += sinf(ang) * wr[2 * i] + cosf(ang) * wr[2 * i + 1];
    }
    g_peproj[id] = acc;
}

// ---------------- pre0: g_pre[t][b][512] = x42 @ M + pe + bias0 (f32x2) ------
// 256 threads: thread owns j0=2t, j1=2t+1; 8-batch tiles; M fully in SMEM.
__global__ __launch_bounds__(256) void k_pre0(const float* __restrict__ xs,
                                              const float* __restrict__ xt) {
    extern __shared__ float sm[];
    float* Msm = sm;               // [42][512]
    float* xT  = sm + 42 * 512;    // [42][8]
    int t = blockIdx.x, tid = threadIdx.x;
    int j0 = tid * 2;
    for (int i = tid; i < 42 * 512; i += 256) Msm[i] = g_Mcomb[i];
    u64 bj0, bj1;
    PACK2(bj0, g_bias0[j0]     + g_peproj[t * 512 + j0]);
    PACK2(bj1, g_bias0[j0 + 1] + g_peproj[t * 512 + j0 + 1]);
    __syncthreads();
    for (int bt = 0; bt < 64; bt++) {
        int bb = bt * 8;
        #pragma unroll
        for (int s = 0; s < 2; s++) {
            int i = tid + s * 256;
            if (i < 128) {
                int b = i >> 4, k = i & 15;
                const float* xp = xs + ((size_t)(bb + b) * TT + t) * 32;
                xT[k * 8 + b] = xp[k] + xp[k + 16];
            } else if (i < 336) {
                int idx = i - 128; int b = idx / 26, k = idx - b * 26;
                xT[(16 + k) * 8 + b] = xt[((size_t)(bb + b) * TT + t) * 26 + k];
            }
        }
        __syncthreads();
        u64 A[8];
        A[0] = bj0; A[1] = bj0; A[2] = bj0; A[3] = bj0;
        A[4] = bj1; A[5] = bj1; A[6] = bj1; A[7] = bj1;
        #pragma unroll 6
        for (int k = 0; k < 42; k++) {
            float2 w = *(const float2*)(Msm + k * 512 + j0);
            u64 wa, wb; PACK2(wa, w.x); PACK2(wb, w.y);
            ulonglong2 h0 = *(const ulonglong2*)(xT + k * 8);
            ulonglong2 h1 = *(const ulonglong2*)(xT + k * 8 + 4);
            FFMA2(A[0], wa, h0.x, A[0]); FFMA2(A[1], wa, h0.y, A[1]);
            FFMA2(A[2], wa, h1.x, A[2]); FFMA2(A[3], wa, h1.y, A[3]);
            FFMA2(A[4], wb, h0.x, A[4]); FFMA2(A[5], wb, h0.y, A[5]);
            FFMA2(A[6], wb, h1.x, A[6]); FFMA2(A[7], wb, h1.y, A[7]);
        }
        unsigned zj0[8], zj1[8];
        UNPK2(zj0[0], zj0[1], A[0]); UNPK2(zj0[2], zj0[3], A[1]);
        UNPK2(zj0[4], zj0[5], A[2]); UNPK2(zj0[6], zj0[7], A[3]);
        UNPK2(zj1[0], zj1[1], A[4]); UNPK2(zj1[2], zj1[3], A[5]);
        UNPK2(zj1[4], zj1[5], A[6]); UNPK2(zj1[6], zj1[7], A[7]);
        size_t po = ((size_t)t * BB + bb) * G4 + j0;
        #pragma unroll
        for (int b = 0; b < 8; b++)
            *(float2*)(g_pre + po + (size_t)b * G4) =
                make_float2(__uint_as_float(zj0[b]), __uint_as_float(zj1[b]));
        __syncthreads();
    }
}

// ---------------- pre1: g_pre = hs0 @ Wih1^T + bias1 (f32x2, hybrid W) -------
__global__ __launch_bounds__(256) void k_pre1(const float* __restrict__ Wih1) {
    extern __shared__ float sm[];
    float* Wsm = sm;               // [96][512]  rows 32..127 of Wih1^T
    float* hT8 = sm + 96 * 512;    // [128][8]
    int t = blockIdx.x, tid = threadIdx.x;
    int j0 = tid * 2;
    u64 w00[32], w11[32];
    #pragma unroll
    for (int k = 0; k < 32; k++) {
        PACK2(w00[k], Wih1[(size_t)j0 * HH + k]);
        PACK2(w11[k], Wih1[(size_t)(j0 + 1) * HH + k]);
    }
    for (int i = tid; i < 96 * 512; i += 256) {
        int kk = i >> 9, jj = i & 511;
        Wsm[i] = Wih1[(size_t)jj * HH + 32 + kk];
    }
    u64 bj0, bj1;
    PACK2(bj0, g_bias1[j0]);
    PACK2(bj1, g_bias1[j0 + 1]);
    __syncthreads();
    for (int bt = 0; bt < 64; bt++) {
        int bb = bt * 8;
        #pragma unroll
        for (int s = 0; s < 4; s++) {
            int i = tid + s * 256;
            int b = i >> 7, k = i & 127;
            hT8[k * 8 + b] = g_hs0[((size_t)t * BB + bb + b) * HH + k];
        }
        __syncthreads();
        u64 A[8];
        A[0] = bj0; A[1] = bj0; A[2] = bj0; A[3] = bj0;
        A[4] = bj1; A[5] = bj1; A[6] = bj1; A[7] = bj1;
        #pragma unroll
        for (int k = 0; k < 32; k++) {
            ulonglong2 h0 = *(const ulonglong2*)(hT8 + k * 8);
            ulonglong2 h1 = *(const ulonglong2*)(hT8 + k * 8 + 4);
            FFMA2(A[0], w00[k], h0.x, A[0]); FFMA2(A[1], w00[k], h0.y, A[1]);
            FFMA2(A[2], w00[k], h1.x, A[2]); FFMA2(A[3], w00[k], h1.y, A[3]);
            FFMA2(A[4], w11[k], h0.x, A[4]); FFMA2(A[5], w11[k], h0.y, A[5]);
            FFMA2(A[6], w11[k], h1.x, A[6]); FFMA2(A[7], w11[k], h1.y, A[7]);
        }
        #pragma unroll 4
        for (int k = 32; k < 128; k++) {
            float2 w = *(const float2*)(Wsm + (k - 32) * 512 + j0);
            u64 wa, wb; PACK2(wa, w.x); PACK2(wb, w.y);
            ulonglong2 h0 = *(const ulonglong2*)(hT8 + k * 8);
            ulonglong2 h1 = *(const ulonglong2*)(hT8 + k * 8 + 4);
            FFMA2(A[0], wa, h0.x, A[0]); FFMA2(A[1], wa, h0.y, A[1]);
            FFMA2(A[2], wa, h1.x, A[2]); FFMA2(A[3], wa, h1.y, A[3]);
            FFMA2(A[4], wb, h0.x, A[4]); FFMA2(A[5], wb, h0.y, A[5]);
            FFMA2(A[6], wb, h1.x, A[6]); FFMA2(A[7], wb, h1.y, A[7]);
        }
        unsigned zj0[8], zj1[8];
        UNPK2(zj0[0], zj0[1], A[0]); UNPK2(zj0[2], zj0[3], A[1]);
        UNPK2(zj0[4], zj0[5], A[2]); UNPK2(zj0[6], zj0[7], A[3]);
        UNPK2(zj1[0], zj1[1], A[4]); UNPK2(zj1[2], zj1[3], A[5]);
        UNPK2(zj1[4], zj1[5], A[6]); UNPK2(zj1[6], zj1[7], A[7]);
        size_t po = ((size_t)t * BB + bb) * G4 + j0;
        #pragma unroll
        for (int b = 0; b < 8; b++)
            *(float2*)(g_pre + po + (size_t)b * G4) =
                make_float2(__uint_as_float(zj0[b]), __uint_as_float(zj1[b]));
        __syncthreads();
    }
}

// ---------------- LSTM recurrence sweep (f32x2, hybrid W, 256 thr) -----------
// 128 CTAs x 4 batch rows. Thread owns gate rows j0=2t, j0+1.
// Gate phase: ids (tid, tid+256) -> (u, b) and (u, b+2); c in registers.
__global__ __launch_bounds__(256) void k_lstm(const float* __restrict__ Whh,
                                              int write_hs, int write_last) {
    extern __shared__ float sm[];
    float* Wsm = sm;                 // [96][512]
    float* zb  = sm + 96 * 512;      // [4][516] z by batch row (padded)
    float* hT  = zb + 4 * 516;       // [128][4]
    int tid = threadIdx.x;
    int j0 = tid * 2;
    int bb = blockIdx.x * 4;
    u64 w00[32], w11[32];
    #pragma unroll
    for (int k = 0; k < 32; k++) {
        PACK2(w00[k], Whh[(size_t)j0 * HH + k]);
        PACK2(w11[k], Whh[(size_t)(j0 + 1) * HH + k]);
    }
    for (int i = tid; i < 96 * 512; i += 256) {
        int kk = i >> 9, jj = i & 511;
        Wsm[i] = Whh[(size_t)jj * HH + 32 + kk];
    }
    hT[tid] = 0.f; hT[tid + 256] = 0.f;
    int u0 = tid & 127, b0 = tid >> 7;   // id0 = tid
    int b1 = b0 + 2;                     // id1 = tid + 256 (same u0)
    float c0 = 0.f, c1 = 0.f, hl0 = 0.f, hl1 = 0.f;
    __syncthreads();

    for (int t = 0; t < TT; t++) {
        size_t po = ((size_t)t * BB + bb) * G4 + j0;
        float2 q0 = *(const float2*)(g_pre + po);             // (p[j0][b], p[j1][b])
        float2 q1 = *(const float2*)(g_pre + po + G4);
        float2 q2 = *(const float2*)(g_pre + po + 2 * G4);
        float2 q3 = *(const float2*)(g_pre + po + 3 * G4);

        u64 A00 = 0, A01 = 0, A10 = 0, A11 = 0;   // (j,bpair): A00=(j0,b01) A01=(j0,b23)
        #pragma unroll
        for (int k = 0; k < 32; k++) {
            ulonglong2 hv = *(const ulonglong2*)(hT + k * 4);
            FFMA2(A00, w00[k], hv.x, A00);
            FFMA2(A01, w00[k], hv.y, A01);
            FFMA2(A10, w11[k], hv.x, A10);
            FFMA2(A11, w11[k], hv.y, A11);
        }
        #pragma unroll 8
        for (int k = 32; k < 128; k++) {
            float2 w = *(const float2*)(Wsm + (k - 32) * 512 + j0);
            u64 wa, wb; PACK2(wa, w.x); PACK2(wb, w.y);
            ulonglong2 hv = *(const ulonglong2*)(hT + k * 4);
            FFMA2(A00, wa, hv.x, A00);
            FFMA2(A01, wa, hv.y, A01);
            FFMA2(A10, wb, hv.x, A10);
            FFMA2(A11, wb, hv.y, A11);
        }
        unsigned a00l, a00h, a01l, a01h, a10l, a10h, a11l, a11h;
        UNPK2(a00l, a00h, A00); UNPK2(a01l, a01h, A01);
        UNPK2(a10l, a10h, A10); UNPK2(a11l, a11h, A11);
        zb[0 * 516 + j0]     = __uint_as_float(a00l) + q0.x;  // z[j0][b0]
        zb[0 * 516 + j0 + 1] = __uint_as_float(a10l) + q0.y;  // z[j1][b0]
        zb[1 * 516 + j0]     = __uint_as_float(a00h) + q1.x;
        zb[1 * 516 + j0 + 1] = __uint_as_float(a10h) + q1.y;
        zb[2 * 516 + j0]     = __uint_as_float(a01l) + q2.x;
        zb[2 * 516 + j0 + 1] = __uint_as_float(a11l) + q2.y;
        zb[3 * 516 + j0]     = __uint_as_float(a01h) + q3.x;
        zb[3 * 516 + j0 + 1] = __uint_as_float(a11h) + q3.y;
        __syncthreads();

        float zi0 = zb[b0 * 516 + u0];
        float zf0 = zb[b0 * 516 + u0 + 128];
        float zg0 = zb[b0 * 516 + u0 + 256];
        float zo0 = zb[b0 * 516 + u0 + 384];
        c0 = sigf(zf0) * c0 + sigf(zi0) * tanhfast(zg0);
        float h0v = sigf(zo0) * tanhfast(c0);
        float zi1 = zb[b1 * 516 + u0];
        float zf1 = zb[b1 * 516 + u0 + 128];
        float zg1 = zb[b1 * 516 + u0 + 256];
        float zo1 = zb[b1 * 516 + u0 + 384];
        c1 = sigf(zf1) * c1 + sigf(zi1) * tanhfast(zg1);
        float h1v = sigf(zo1) * tanhfast(c1);
        hl0 = h0v; hl1 = h1v;
        hT[u0 * 4 + b0] = h0v;
        hT[u0 * 4 + b1] = h1v;
        if (write_hs) {
            g_hs0[((size_t)t * BB + bb + b0) * HH + u0] = h0v;
            g_hs0[((size_t)t * BB + bb + b1) * HH + u0] = h1v;
        }
        __syncthreads();
    }
    if (write_last) {
        g_last[(bb + b0) * HH + u0] = hl0;
        g_last[(bb + b1) * HH + u0] = hl1;
    }
}

// ---------------- MLP head (unchanged, passing) ------------------------------
__global__ __launch_bounds__(128) void k_head(
                       const float* __restrict__ W1, const float* __restrict__ b1,
                       const float* __restrict__ W2, const float* __restrict__ b2,
                       const float* __restrict__ W3, const float* __restrict__ b3,
                       float* __restrict__ out) {
    __shared__ float xin[128], y1[128], y2[64];
    int b = blockIdx.x, j = threadIdx.x;
    xin[j] = g_last[b * HH + j];
    __syncthreads();
    float s = b1[j];
    #pragma unroll 4
    for (int k = 0; k < 128; k++) s += xin[k] * W1[j * 128 + k];
    y1[j] = fmaxf(s, 0.f);
    __syncthreads();
    if (j < 64) {
        float s2 = b2[j];
        #pragma unroll 4
        for (int k = 0; k < 128; k++) s2 += y1[k] * W2[j * 128 + k];
        y2[j] = fmaxf(s2, 0.f);
    }
    __syncthreads();
    if (j < 26) {
        float s3 = b3[j];
        #pragma unroll 4
        for (int k = 0; k < 64; k++) s3 += y2[k] * W3[j * 64 + k];
        out[b * 26 + j] = s3;
    }
}

// ---------------- launch -----------------------------------------------------
extern "C" void kernel_launch(void* const* d_in, const int* in_sizes, int n_in,
                              void* d_out, int out_size) {
    const float* xs   = (const float*)d_in[0];
    const float* xt   = (const float*)d_in[1];
    const float* Wgcn = (const float*)d_in[2];
    const float* bgcn = (const float*)d_in[3];
    const float* Wte  = (const float*)d_in[4];
    const float* bte  = (const float*)d_in[5];
    const float* Wih0 = (const float*)d_in[6];
    const float* Whh0 = (const float*)d_in[7];
    const float* bih0 = (const float*)d_in[8];
    const float* bhh0 = (const float*)d_in[9];
    const float* Wih1 = (const float*)d_in[10];
    const float* Whh1 = (const float*)d_in[11];
    const float* bih1 = (const float*)d_in[12];
    const float* bhh1 = (const float*)d_in[13];
    const float* W1   = (const float*)d_in[14];
    const float* b1   = (const float*)d_in[15];
    const float* W2   = (const float*)d_in[16];
    const float* b2   = (const float*)d_in[17];
    const float* W3   = (const float*)d_in[18];
    const float* b3   = (const float*)d_in[19];

    const int SM_PRE0 = (42 * 512 + 42 * 8) * 4;                  //  87,360 B
    const int SM_PRE1 = (96 * 512 + 128 * 8) * 4;                 // 200,704 B
    const int SM_LSTM = (96 * 512 + 4 * 516 + 128 * 4) * 4;       // 206,912 B
    cudaFuncSetAttribute(k_pre0, cudaFuncAttributeMaxDynamicSharedMemorySize, SM_PRE0);
    cudaFuncSetAttribute(k_pre1, cudaFuncAttributeMaxDynamicSharedMemorySize, SM_PRE1);
    cudaFuncSetAttribute(k_lstm, cudaFuncAttributeMaxDynamicSharedMemorySize, SM_LSTM);

    k_comb<<<1, 512>>>(Wgcn, bgcn, Wte, bte, Wih0, bih0, bhh0, bih1, bhh1);
    k_pe<<<(TT * 512 + 255) / 256, 256>>>(Wih0);
    k_pre0<<<TT, 256, SM_PRE0>>>(xs, xt);
    k_lstm<<<BB / 4, 256, SM_LSTM>>>(Whh0, 1, 0);   // layer 0 -> hs0
    k_pre1<<<TT, 256, SM_PRE1>>>(Wih1);             // g_pre := pre1
    k_lstm<<<BB / 4, 256, SM_LSTM>>>(Whh1, 0, 1);   // layer 1 -> last
    k_head<<<BB, 128>>>(W1, b1, W2, b2, W3, b3, (float*)d_out);
}